// round 8
// baseline (speedup 1.0000x reference)
#include <cuda_runtime.h>
#include <cuda_bf16.h>

// ---------------------------------------------------------------------------
// FSSConv1dCell: conv3(g8)+shuffle -> conv3(g8)+shuffle -> sortattn -> conv5(g8)
// B=8, C=256, L=4096, groups=8, cpg=32
// ---------------------------------------------------------------------------

typedef unsigned long long ull;

#define B_  8
#define C_  256
#define L0  4096
#define L1  4094   // after conv1 (K=3)
#define L2  4092   // after conv2 (K=3)
#define L4  4088   // after conv3 (K=5)
#define PADL 4096  // row stride of intermediate buffers

// intermediate buffers (device globals: no allocation allowed)
__device__ float g_h1[B_ * C_ * PADL];
__device__ float g_h2[B_ * C_ * PADL];
__device__ float g_hm[B_ * C_ * PADL];
// duplicated+transposed attention weights: [j][o] each entry = (w,w)
__device__ float2 g_wa1D[64 * 256];
__device__ float2 g_wa2D[32 * 256];

// ---- packed f32x2 helpers (sm_103a FFMA2 path, PTX-only) ----
__device__ __forceinline__ ull pk2(float lo, float hi) {
    ull r; asm("mov.b64 %0, {%1,%2};" : "=l"(r) : "f"(lo), "f"(hi)); return r;
}
__device__ __forceinline__ ull ffma2(ull a, ull b, ull c) {
    ull d; asm("fma.rn.f32x2 %0, %1, %2, %3;" : "=l"(d) : "l"(a), "l"(b), "l"(c)); return d;
}
__device__ __forceinline__ float2 unpk(ull v) {
    float2 f; asm("mov.b64 {%0,%1}, %2;" : "=f"(f.x), "=f"(f.y) : "l"(v)); return f;
}

// ---------------------------------------------------------------------------
// prep: transpose + duplicate attention weights
// wa1: [256][64]  -> g_wa1D[j*256+o] = (w,w)
// wa2: [256][32]  -> g_wa2D[j*256+o] = (w,w)
// ---------------------------------------------------------------------------
__global__ void prep_kernel(const float* __restrict__ wa1, const float* __restrict__ wa2) {
    int t = blockIdx.x * blockDim.x + threadIdx.x;
    if (t < 256 * 64) {
        int o = t >> 6, j = t & 63;
        float v = wa1[t];
        g_wa1D[j * 256 + o] = make_float2(v, v);
    }
    if (t < 256 * 32) {
        int o = t >> 5, j = t & 31;
        float v = wa2[t];
        g_wa2D[j * 256 + o] = make_float2(v, v);
    }
}

// ---------------------------------------------------------------------------
// grouped conv1d, K taps, optional channel shuffle on output.
// block: 256 threads. tile: 256 output columns, one (batch, group) per block.
// thread: cg = tid&63 -> 4 columns, cq = tid>>6 -> 8 out channels.
// smem: in tile [32][264], dup weights float2 [32][K][32], dup bias [32]
// ---------------------------------------------------------------------------
template <int K, bool SHUF>
__global__ void conv_kernel(const float* __restrict__ in, int Lin, int inStride,
                            float* __restrict__ out, int Lout, int outStride,
                            const float* __restrict__ w, const float* __restrict__ bias)
{
    extern __shared__ float smem[];
    float*  sh_in = smem;                                 // 32*264
    float2* sh_wd = (float2*)(smem + 32 * 264);           // [32][K][32]
    float2* sh_bd = sh_wd + 32 * K * 32;                  // [32]

    const int tid  = threadIdx.x;
    const int tile = blockIdx.x, gidx = blockIdx.y, b = blockIdx.z;
    const int t0 = tile * 256;
    const int g0 = gidx * 32;

    // --- stage input tile (group's 32 channels, cols t0 .. t0+255+K-1) ---
    {
        int ci = tid >> 3, l8 = tid & 7;
        const float* rp = in + ((size_t)b * C_ + g0 + ci) * (size_t)inStride;
        for (int j = l8 * 4; j < 256 + K - 1; j += 32) {
            int c0 = t0 + j;
            float4 v;
            if (c0 + 3 < Lin) {
                v = *(const float4*)(rp + c0);
            } else {
                v.x = (c0     < Lin) ? rp[c0]     : 0.f;
                v.y = (c0 + 1 < Lin) ? rp[c0 + 1] : 0.f;
                v.z = (c0 + 2 < Lin) ? rp[c0 + 2] : 0.f;
                v.w = (c0 + 3 < Lin) ? rp[c0 + 3] : 0.f;
            }
            *(float4*)&sh_in[ci * 264 + j] = v;
        }
    }
    // --- stage duplicated weights [ci][k][co] and bias ---
    for (int idx = tid; idx < 32 * K * 32; idx += 256) {
        int ci = idx / (K * 32), r = idx % (K * 32);
        int k = r >> 5, co = r & 31;
        float v = w[((size_t)(g0 + co)) * (32 * K) + ci * K + k];
        sh_wd[idx] = make_float2(v, v);
    }
    if (tid < 32) { float v = bias[g0 + tid]; sh_bd[tid] = make_float2(v, v); }
    __syncthreads();

    const int cg = tid & 63;   // column group: 4 columns
    const int cq = tid >> 6;   // out-channel group: 8 channels

    ull acc[8][2];
#pragma unroll
    for (int r = 0; r < 8; r++) {
        ull bb = *(const ull*)&sh_bd[cq * 8 + r];
        acc[r][0] = bb; acc[r][1] = bb;
    }

    const float* ip = &sh_in[cg * 4];
#pragma unroll 4
    for (int ci = 0; ci < 32; ci++) {
        float v[K + 3];
        float4 t4 = *(const float4*)(ip + ci * 264);
        v[0] = t4.x; v[1] = t4.y; v[2] = t4.z; v[3] = t4.w;
        if (K == 3) {
            float2 t2 = *(const float2*)(ip + ci * 264 + 4);
            v[4] = t2.x; v[5] = t2.y;
        } else {
            float4 u4 = *(const float4*)(ip + ci * 264 + 4);
            v[4] = u4.x; v[5] = u4.y; v[6] = u4.z; v[7] = u4.w;
        }
        // pairs pr[j] = (v[j], v[j+1]); acc[.][1] needs pr[k+2] up to k=K-1
        // -> indices 0 .. K+1, so the array must hold K+2 entries.
        ull pr[K + 2];
#pragma unroll
        for (int j = 0; j < K + 2; j++) pr[j] = pk2(v[j], v[j + 1]);

        const float2* wrow = &sh_wd[ci * K * 32];
#pragma unroll
        for (int r = 0; r < 8; r++) {
#pragma unroll
            for (int k = 0; k < K; k++) {
                ull wk = *(const ull*)&wrow[k * 32 + cq * 8 + r];
                acc[r][0] = ffma2(pr[k],     wk, acc[r][0]);
                acc[r][1] = ffma2(pr[k + 2], wk, acc[r][1]);
            }
        }
    }

    // --- store (optionally shuffled: c' = co*8 + gidx) ---
    const int colBase = t0 + cg * 4;
#pragma unroll
    for (int r = 0; r < 8; r++) {
        int co = cq * 8 + r;
        int oc = SHUF ? (co * 8 + gidx) : (g0 + co);
        float* op = out + ((size_t)b * C_ + oc) * (size_t)outStride;
        float2 a0 = unpk(acc[r][0]), a1 = unpk(acc[r][1]);
        if (colBase + 3 < Lout) {
            float4 q; q.x = a0.x; q.y = a0.y; q.z = a1.x; q.w = a1.y;
            *(float4*)(op + colBase) = q;
        } else {
            if (colBase     < Lout) op[colBase]     = a0.x;
            if (colBase + 1 < Lout) op[colBase + 1] = a0.y;
            if (colBase + 2 < Lout) op[colBase + 2] = a1.x;
            if (colBase + 3 < Lout) op[colBase + 3] = a1.y;
        }
    }
}

// ---------------------------------------------------------------------------
// warp-level bitonic sort of 256 values, 8 regs/lane, element e = r*32 + lane
// ---------------------------------------------------------------------------
__device__ __forceinline__ void bitonic256(float v[8], int lane) {
#pragma unroll
    for (int k = 2; k <= 256; k <<= 1) {
#pragma unroll
        for (int j = k >> 1; j > 0; j >>= 1) {
            if (j >= 32) {
                int jr = j >> 5;
#pragma unroll
                for (int r = 0; r < 8; r++) {
                    if ((r & jr) == 0) {
                        int r2 = r | jr;
                        bool up = (((r * 32) & k) == 0);
                        float a = v[r], b = v[r2];
                        float mn = fminf(a, b), mx = fmaxf(a, b);
                        v[r]  = up ? mn : mx;
                        v[r2] = up ? mx : mn;
                    }
                }
            } else {
#pragma unroll
                for (int r = 0; r < 8; r++) {
                    int e = r * 32 + lane;
                    float p = __shfl_xor_sync(0xffffffffu, v[r], j);
                    bool keepMin = (((e & j) == 0) == ((e & k) == 0));
                    v[r] = keepMin ? fminf(v[r], p) : fmaxf(v[r], p);
                }
            }
        }
    }
}

// padded index for 256-entry column buffers (kills 64-stride bank conflicts)
__device__ __forceinline__ int pidx(int s) { return s + 2 * (s >> 6); }

// ---------------------------------------------------------------------------
// SortAttn fused kernel:  h2 -> hm = h2 * sigmoid(conv_a2(shuffle(conv_a1(cat(sort(h2),h2)))))
// block: 256 threads (8 warps), 32 columns of one batch. warp handles 4 columns.
// Group trick: conv_a1 groups 0-3 read only sorted[], groups 4-7 read only h[].
// ---------------------------------------------------------------------------
__global__ void attn_kernel(const float* __restrict__ h2, float* __restrict__ hm,
                            const float* __restrict__ ba1, const float* __restrict__ ba2)
{
    extern __shared__ float smem[];
    float* sh_h = smem;                    // [256][33]
    float* sh_s = smem + 256 * 33;         // 8 warps * 4 cols * 264

    const int tid = threadIdx.x, lane = tid & 31, wid = tid >> 5;
    const int b = blockIdx.y;
    const int t0 = blockIdx.x * 32;

    // --- stage h2 tile: thread tid = channel, 32 columns ---
    {
        const float* rp = h2 + ((size_t)b * C_ + tid) * PADL + t0;
#pragma unroll
        for (int j = 0; j < 32; j += 4) {
            float4 v;
            if (t0 + j + 3 < L2) {
                v = *(const float4*)(rp + j);
            } else {
                v.x = (t0 + j     < L2) ? rp[j]     : 0.f;
                v.y = (t0 + j + 1 < L2) ? rp[j + 1] : 0.f;
                v.z = (t0 + j + 2 < L2) ? rp[j + 2] : 0.f;
                v.w = (t0 + j + 3 < L2) ? rp[j + 3] : 0.f;
            }
            sh_h[tid * 33 + j]     = v.x;
            sh_h[tid * 33 + j + 1] = v.y;
            sh_h[tid * 33 + j + 2] = v.z;
            sh_h[tid * 33 + j + 3] = v.w;
        }
    }
    __syncthreads();

    float* shS = sh_s + wid * (4 * 264);
    const int col0 = wid * 4;

    // --- sort the warp's 4 columns ---
#pragma unroll
    for (int cc = 0; cc < 4; cc++) {
        float v[8];
#pragma unroll
        for (int r = 0; r < 8; r++) v[r] = sh_h[(r * 32 + lane) * 33 + col0 + cc];
        bitonic256(v, lane);
#pragma unroll
        for (int r = 0; r < 8; r++) {
            int s = r * 32 + lane;
            shS[cc * 264 + pidx(s)] = v[r];
        }
    }
    __syncwarp();

    const int gq = lane >> 2;          // group of this lane's 8 out channels
    const int qb = (gq & 3) * 64;      // base within sorted/h half
    const int o0 = lane * 8;           // first out channel

    // --- conv_a1 (1x1, 64 in): acc over 4 columns ---
    ull acc[8][2];
    {
        float4 b0 = *(const float4*)(ba1 + o0);
        float4 b1 = *(const float4*)(ba1 + o0 + 4);
        float bv[8] = {b0.x, b0.y, b0.z, b0.w, b1.x, b1.y, b1.z, b1.w};
#pragma unroll
        for (int r = 0; r < 8; r++) { ull bb = pk2(bv[r], bv[r]); acc[r][0] = bb; acc[r][1] = bb; }
    }
#pragma unroll 4
    for (int j = 0; j < 64; j++) {
        float i0, i1, i2, i3;
        if (gq < 4) {
            int a = pidx(qb + j);
            i0 = shS[a]; i1 = shS[264 + a]; i2 = shS[528 + a]; i3 = shS[792 + a];
        } else {
            const float* hp = &sh_h[(qb + j) * 33 + col0];
            i0 = hp[0]; i1 = hp[1]; i2 = hp[2]; i3 = hp[3];
        }
        ull p01 = pk2(i0, i1), p23 = pk2(i2, i3);
        const float2* wp = g_wa1D + j * 256 + o0;
#pragma unroll
        for (int r = 0; r < 8; r += 2) {
            ulonglong2 u = *(const ulonglong2*)&wp[r];
            acc[r][0]     = ffma2(p01, u.x, acc[r][0]);
            acc[r][1]     = ffma2(p23, u.x, acc[r][1]);
            acc[r + 1][0] = ffma2(p01, u.y, acc[r + 1][0]);
            acc[r + 1][1] = ffma2(p23, u.y, acc[r + 1][1]);
        }
    }
    __syncwarp();

    // --- write a1 shuffled into shS (sorted data dead now) ---
#pragma unroll
    for (int r = 0; r < 8; r++) {
        int o = o0 + r;
        int gi = o >> 5, jw = o & 31;
        int a = pidx(jw * 8 + gi);
        float2 a0 = unpk(acc[r][0]), a1v = unpk(acc[r][1]);
        shS[a] = a0.x; shS[264 + a] = a0.y; shS[528 + a] = a1v.x; shS[792 + a] = a1v.y;
    }
    __syncwarp();

    // --- conv_a2 (1x1, 32 in) ---
    ull acc2[8][2];
    {
        float4 b0 = *(const float4*)(ba2 + o0);
        float4 b1 = *(const float4*)(ba2 + o0 + 4);
        float bv[8] = {b0.x, b0.y, b0.z, b0.w, b1.x, b1.y, b1.z, b1.w};
#pragma unroll
        for (int r = 0; r < 8; r++) { ull bb = pk2(bv[r], bv[r]); acc2[r][0] = bb; acc2[r][1] = bb; }
    }
#pragma unroll 4
    for (int j = 0; j < 32; j++) {
        int a = pidx(gq * 32 + j);
        float i0 = shS[a], i1 = shS[264 + a], i2 = shS[528 + a], i3 = shS[792 + a];
        ull p01 = pk2(i0, i1), p23 = pk2(i2, i3);
        const float2* wp = g_wa2D + j * 256 + o0;
#pragma unroll
        for (int r = 0; r < 8; r += 2) {
            ulonglong2 u = *(const ulonglong2*)&wp[r];
            acc2[r][0]     = ffma2(p01, u.x, acc2[r][0]);
            acc2[r][1]     = ffma2(p23, u.x, acc2[r][1]);
            acc2[r + 1][0] = ffma2(p01, u.y, acc2[r + 1][0]);
            acc2[r + 1][1] = ffma2(p23, u.y, acc2[r + 1][1]);
        }
    }

    // --- sigmoid gate, multiply by h, store hm ---
#pragma unroll
    for (int r = 0; r < 8; r++) {
        int ch = o0 + r;
        float2 a0 = unpk(acc2[r][0]), a1v = unpk(acc2[r][1]);
        float s0 = 1.f / (1.f + __expf(-a0.x));
        float s1 = 1.f / (1.f + __expf(-a0.y));
        float s2 = 1.f / (1.f + __expf(-a1v.x));
        float s3 = 1.f / (1.f + __expf(-a1v.y));
        const float* hp = &sh_h[ch * 33 + col0];
        float* op = hm + ((size_t)b * C_ + ch) * PADL + t0 + col0;
        if (t0 + col0 + 3 < L2) {
            float4 q; q.x = hp[0] * s0; q.y = hp[1] * s1; q.z = hp[2] * s2; q.w = hp[3] * s3;
            *(float4*)op = q;
        } else {
            if (t0 + col0     < L2) op[0] = hp[0] * s0;
            if (t0 + col0 + 1 < L2) op[1] = hp[1] * s1;
            if (t0 + col0 + 2 < L2) op[2] = hp[2] * s2;
            if (t0 + col0 + 3 < L2) op[3] = hp[3] * s3;
        }
    }
}

// ---------------------------------------------------------------------------
extern "C" void kernel_launch(void* const* d_in, const int* in_sizes, int n_in,
                              void* d_out, int out_size)
{
    const float* x   = (const float*)d_in[0];
    const float* w1  = (const float*)d_in[1];
    const float* b1  = (const float*)d_in[2];
    const float* w2  = (const float*)d_in[3];
    const float* b2  = (const float*)d_in[4];
    const float* wa1 = (const float*)d_in[5];
    const float* ba1 = (const float*)d_in[6];
    const float* wa2 = (const float*)d_in[7];
    const float* ba2 = (const float*)d_in[8];
    const float* w3  = (const float*)d_in[9];
    const float* b3  = (const float*)d_in[10];
    float* y = (float*)d_out;

    float *h1p, *h2p, *hmp;
    cudaGetSymbolAddress((void**)&h1p, g_h1);
    cudaGetSymbolAddress((void**)&h2p, g_h2);
    cudaGetSymbolAddress((void**)&hmp, g_hm);

    const int SM3 = 32 * 264 * 4 + 32 * 3 * 32 * 8 + 32 * 8;   // 58624
    const int SM5 = 32 * 264 * 4 + 32 * 5 * 32 * 8 + 32 * 8;   // 75008
    const int SMA = 256 * 33 * 4 + 8 * 4 * 264 * 4;            // 67584

    cudaFuncSetAttribute(conv_kernel<3, true>,  cudaFuncAttributeMaxDynamicSharedMemorySize, SM3);
    cudaFuncSetAttribute(conv_kernel<5, false>, cudaFuncAttributeMaxDynamicSharedMemorySize, SM5);
    cudaFuncSetAttribute(attn_kernel,           cudaFuncAttributeMaxDynamicSharedMemorySize, SMA);

    prep_kernel<<<64, 256>>>(wa1, wa2);

    // conv1 + shuffle : x[*,4096] -> g_h1[*,4094] (padded stride 4096)
    conv_kernel<3, true><<<dim3(16, 8, B_), 256, SM3>>>(x, L0, L0, h1p, L1, PADL, w1, b1);
    // conv2 + shuffle : g_h1 -> g_h2[*,4092]
    conv_kernel<3, true><<<dim3(16, 8, B_), 256, SM3>>>(h1p, L1, PADL, h2p, L2, PADL, w2, b2);
    // sort attention  : g_h2 -> g_hm
    attn_kernel<<<dim3(128, B_), 256, SMA>>>(h2p, hmp, ba1, ba2);
    // conv3 (K=5)     : g_hm -> y[*,4088]
    conv_kernel<5, false><<<dim3(16, 8, B_), 256, SM5>>>(hmp, L2, PADL, y, L4, L4, w3, b3);
}

// round 9
// speedup vs baseline: 1.2116x; 1.2116x over previous
#include <cuda_runtime.h>
#include <cuda_bf16.h>

// ---------------------------------------------------------------------------
// FSSConv1dCell: conv3(g8)+shuffle -> conv3(g8)+shuffle -> sortattn -> conv5(g8)
// B=8, C=256, L=4096, groups=8, cpg=32
// ---------------------------------------------------------------------------

typedef unsigned long long ull;

#define B_  8
#define C_  256
#define L0  4096
#define L1  4094   // after conv1 (K=3)
#define L2  4092   // after conv2 (K=3)
#define L4  4088   // after conv3 (K=5)
#define PADL 4096  // row stride of intermediate buffers
#define STR  258   // attn smem column stride (even; 129 f2 odd -> conflict-free LDS.64)

// intermediate buffers (device globals: no allocation allowed)
__device__ float g_h1[B_ * C_ * PADL];
__device__ float g_h2[B_ * C_ * PADL];
__device__ float g_hm[B_ * C_ * PADL];

// ---- packed f32x2 helpers (sm_103a FFMA2 path, PTX-only) ----
__device__ __forceinline__ ull pk2(float lo, float hi) {
    ull r; asm("mov.b64 %0, {%1,%2};" : "=l"(r) : "f"(lo), "f"(hi)); return r;
}
__device__ __forceinline__ ull ffma2(ull a, ull b, ull c) {
    ull d; asm("fma.rn.f32x2 %0, %1, %2, %3;" : "=l"(d) : "l"(a), "l"(b), "l"(c)); return d;
}
__device__ __forceinline__ float2 unpk(ull v) {
    float2 f; asm("mov.b64 {%0,%1}, %2;" : "=f"(f.x), "=f"(f.y) : "l"(v)); return f;
}

// ---------------------------------------------------------------------------
// grouped conv1d, K taps, optional channel shuffle on output.
// block: 256 threads. tile: 512 output columns, one (batch, group) per block.
// thread: cg = tid&63 -> 8 columns, cq = tid>>6 -> 8 out channels.
// smem: in tile [32][520], dup weights float2 [32][K][32], dup bias [32]
// ---------------------------------------------------------------------------
#define RS 520

template <int K, bool SHUF>
__global__ void conv_kernel(const float* __restrict__ in, int Lin, int inStride,
                            float* __restrict__ out, int Lout, int outStride,
                            const float* __restrict__ w, const float* __restrict__ bias)
{
    extern __shared__ float smem[];
    float*  sh_in = smem;                                 // 32*RS
    float2* sh_wd = (float2*)(smem + 32 * RS);            // [32][K][32]
    float2* sh_bd = sh_wd + 32 * K * 32;                  // [32]

    const int tid  = threadIdx.x;
    const int tile = blockIdx.x, gidx = blockIdx.y, b = blockIdx.z;
    const int t0 = tile * 512;
    const int g0 = gidx * 32;

    // --- stage input tile (group's 32 channels, cols t0 .. t0+511+K-1) ---
    {
        int ci = tid >> 3, l8 = tid & 7;
        const float* rp = in + ((size_t)b * C_ + g0 + ci) * (size_t)inStride;
        for (int j = l8 * 4; j < 512 + K - 1; j += 32) {
            int c0 = t0 + j;
            float4 v;
            if (c0 + 3 < Lin) {
                v = *(const float4*)(rp + c0);
            } else {
                v.x = (c0     < Lin) ? rp[c0]     : 0.f;
                v.y = (c0 + 1 < Lin) ? rp[c0 + 1] : 0.f;
                v.z = (c0 + 2 < Lin) ? rp[c0 + 2] : 0.f;
                v.w = (c0 + 3 < Lin) ? rp[c0 + 3] : 0.f;
            }
            *(float4*)&sh_in[ci * RS + j] = v;
        }
    }
    // --- stage duplicated weights [ci][k][co] and bias ---
    for (int idx = tid; idx < 32 * K * 32; idx += 256) {
        int ci = idx / (K * 32), r = idx % (K * 32);
        int k = r >> 5, co = r & 31;
        float v = w[((size_t)(g0 + co)) * (32 * K) + ci * K + k];
        sh_wd[idx] = make_float2(v, v);
    }
    if (tid < 32) { float v = bias[g0 + tid]; sh_bd[tid] = make_float2(v, v); }
    __syncthreads();

    const int cg = tid & 63;   // column group: 8 columns
    const int cq = tid >> 6;   // out-channel group: 8 channels

    ull acc[8][4];
#pragma unroll
    for (int r = 0; r < 8; r++) {
        ull bb = *(const ull*)&sh_bd[cq * 8 + r];
        acc[r][0] = bb; acc[r][1] = bb; acc[r][2] = bb; acc[r][3] = bb;
    }

    const float* ip = &sh_in[cg * 8];
#pragma unroll 4
    for (int ci = 0; ci < 32; ci++) {
        const float* row = ip + ci * RS;
        float v[K + 7];
        float4 t4 = *(const float4*)(row);
        float4 u4 = *(const float4*)(row + 4);
        v[0] = t4.x; v[1] = t4.y; v[2] = t4.z; v[3] = t4.w;
        v[4] = u4.x; v[5] = u4.y; v[6] = u4.z; v[7] = u4.w;
        if (K == 3) {
            float2 t2 = *(const float2*)(row + 8);
            v[8] = t2.x; v[9] = t2.y;
        } else {
            float4 w4 = *(const float4*)(row + 8);
            v[8] = w4.x; v[9] = w4.y; v[10] = w4.z; v[11] = w4.w;
        }
        // pairs pr[j] = (v[j], v[j+1]); acc[.][m] needs pr[k+2m], k<K, m<4
        ull pr[K + 6];
#pragma unroll
        for (int j = 0; j < K + 6; j++) pr[j] = pk2(v[j], v[j + 1]);

        const float2* wrow = &sh_wd[ci * K * 32];
#pragma unroll
        for (int r = 0; r < 8; r++) {
#pragma unroll
            for (int k = 0; k < K; k++) {
                ull wk = *(const ull*)&wrow[k * 32 + cq * 8 + r];
                acc[r][0] = ffma2(pr[k],     wk, acc[r][0]);
                acc[r][1] = ffma2(pr[k + 2], wk, acc[r][1]);
                acc[r][2] = ffma2(pr[k + 4], wk, acc[r][2]);
                acc[r][3] = ffma2(pr[k + 6], wk, acc[r][3]);
            }
        }
    }

    // --- store (optionally shuffled: c' = co*8 + gidx) ---
    const int colBase = t0 + cg * 8;
#pragma unroll
    for (int r = 0; r < 8; r++) {
        int co = cq * 8 + r;
        int oc = SHUF ? (co * 8 + gidx) : (g0 + co);
        float* op = out + ((size_t)b * C_ + oc) * (size_t)outStride;
        float2 a0 = unpk(acc[r][0]), a1 = unpk(acc[r][1]);
        float2 a2 = unpk(acc[r][2]), a3 = unpk(acc[r][3]);
        if (colBase + 7 < Lout) {
            float4 q0; q0.x = a0.x; q0.y = a0.y; q0.z = a1.x; q0.w = a1.y;
            float4 q1; q1.x = a2.x; q1.y = a2.y; q1.z = a3.x; q1.w = a3.y;
            *(float4*)(op + colBase)     = q0;
            *(float4*)(op + colBase + 4) = q1;
        } else {
            float vv[8] = {a0.x, a0.y, a1.x, a1.y, a2.x, a2.y, a3.x, a3.y};
#pragma unroll
            for (int m = 0; m < 8; m++)
                if (colBase + m < Lout) op[colBase + m] = vv[m];
        }
    }
}

// ---------------------------------------------------------------------------
// warp-level bitonic sort of 256 values, 8 regs/lane, element e = r*32 + lane
// ---------------------------------------------------------------------------
__device__ __forceinline__ void bitonic256(float v[8], int lane) {
#pragma unroll
    for (int k = 2; k <= 256; k <<= 1) {
#pragma unroll
        for (int j = k >> 1; j > 0; j >>= 1) {
            if (j >= 32) {
                int jr = j >> 5;
#pragma unroll
                for (int r = 0; r < 8; r++) {
                    if ((r & jr) == 0) {
                        int r2 = r | jr;
                        bool up = (((r * 32) & k) == 0);
                        float a = v[r], b = v[r2];
                        float mn = fminf(a, b), mx = fmaxf(a, b);
                        v[r]  = up ? mn : mx;
                        v[r2] = up ? mx : mn;
                    }
                }
            } else {
#pragma unroll
                for (int r = 0; r < 8; r++) {
                    int e = r * 32 + lane;
                    float p = __shfl_xor_sync(0xffffffffu, v[r], j);
                    bool keepMin = (((e & j) == 0) == ((e & k) == 0));
                    v[r] = keepMin ? fminf(v[r], p) : fmaxf(v[r], p);
                }
            }
        }
    }
}

// ---------------------------------------------------------------------------
// SortAttn fused kernel:  h2 -> hm = h2 * sigmoid(conv_a2(shuffle(conv_a1(cat(sort(h2),h2)))))
// block: 256 threads (8 warps), tile = 32 columns of one batch.
// Phase layout:
//   stage:   warp w loads channels w*32..w*32+31 coalesced, writes transposed
//            sh_ht[col][ch] (stride STR).
//   sort:    warp w sorts cols w*4..w*4+3 (bitonic in regs+shfl) -> sh_srt[col][rank]
//   conv_a1: warp w <-> oc-group w (exactly the g=8 concat split: groups 0-3 read
//            only sorted, 4-7 only h). lane <-> column; 64-input slice lives in
//            32 packed f32x2 registers; weights are broadcast LDS.128 from sw1.
//   conv_a2: same pattern on shuffled a1 (sh_a1[col][ch']), then sigmoid gate,
//            coalesced STG per out-channel row.
// ---------------------------------------------------------------------------
__global__ void attn_kernel(const float* __restrict__ h2, float* __restrict__ hm,
                            const float* __restrict__ wa1, const float* __restrict__ ba1,
                            const float* __restrict__ wa2, const float* __restrict__ ba2)
{
    extern __shared__ float smem[];
    float* sw1    = smem;                       // 16384 floats (wa1: [256][64])
    float* sw2    = smem + 16384;               // 8192  floats (wa2: [256][32])
    float* sh_ht  = smem + 24576;               // [32][STR]  h transposed
    float* sh_srt = sh_ht  + 32 * STR;          // [32][STR]  sorted
    float* sh_a1  = sh_srt + 32 * STR;          // [32][STR]  a1 shuffled transposed

    const int tid = threadIdx.x, lane = tid & 31, w = tid >> 5;
    const int b = blockIdx.y;
    const int t0 = blockIdx.x * 32;

    // --- stage weights into smem (raw layout; consecutive j = natural f32x2 pairs)
    {
        const float4* s1 = (const float4*)wa1; float4* d1 = (float4*)sw1;
        for (int i = tid; i < 4096; i += 256) d1[i] = s1[i];
        const float4* s2 = (const float4*)wa2; float4* d2 = (float4*)sw2;
        for (int i = tid; i < 2048; i += 256) d2[i] = s2[i];
    }

    // --- stage h2 tile transposed: warp w handles channels w*32..w*32+31 ---
    {
        int ch4 = lane >> 3, colq = lane & 7;   // 4 channels x 8 float4-cols per iter
        int c0 = t0 + colq * 4;
#pragma unroll
        for (int it = 0; it < 8; it++) {
            int ch = w * 32 + it * 4 + ch4;
            const float* rp = h2 + ((size_t)b * C_ + ch) * PADL + c0;
            float4 v;
            if (c0 + 3 < L2) {
                v = *(const float4*)rp;
            } else {
                v.x = (c0     < L2) ? rp[0] : 0.f;
                v.y = (c0 + 1 < L2) ? rp[1] : 0.f;
                v.z = (c0 + 2 < L2) ? rp[2] : 0.f;
                v.w = (c0 + 3 < L2) ? rp[3] : 0.f;
            }
            sh_ht[(colq * 4 + 0) * STR + ch] = v.x;
            sh_ht[(colq * 4 + 1) * STR + ch] = v.y;
            sh_ht[(colq * 4 + 2) * STR + ch] = v.z;
            sh_ht[(colq * 4 + 3) * STR + ch] = v.w;
        }
    }
    __syncthreads();

    // --- sort: warp w sorts columns w*4 .. w*4+3 ---
#pragma unroll
    for (int cc = 0; cc < 4; cc++) {
        int col = w * 4 + cc;
        float v[8];
#pragma unroll
        for (int r = 0; r < 8; r++) v[r] = sh_ht[col * STR + r * 32 + lane];
        bitonic256(v, lane);
#pragma unroll
        for (int r = 0; r < 8; r++) sh_srt[col * STR + r * 32 + lane] = v[r];
    }
    __syncthreads();

    // --- conv_a1: warp w = group w; lane = column ---
    {
        const float* ibase = (w < 4 ? sh_srt : sh_ht) + lane * STR + (w & 3) * 64;
        ull inp[32];
#pragma unroll
        for (int q = 0; q < 32; q++) inp[q] = *(const ull*)(ibase + 2 * q);

        for (int ocl = 0; ocl < 32; ocl++) {
            int oc = w * 32 + ocl;
            const ulonglong2* wr = (const ulonglong2*)(sw1 + oc * 64);  // broadcast
            ull acc = 0ULL;
#pragma unroll
            for (int q = 0; q < 16; q++) {
                ulonglong2 u = wr[q];
                acc = ffma2(inp[2 * q],     u.x, acc);
                acc = ffma2(inp[2 * q + 1], u.y, acc);
            }
            float2 s = unpk(acc);
            float val = s.x + s.y + __ldg(ba1 + oc);
            // shuffled channel: c' = (oc&31)*8 + (oc>>5) = ocl*8 + w
            sh_a1[lane * STR + ocl * 8 + w] = val;
        }
    }
    __syncthreads();

    // --- conv_a2 + sigmoid gate + store ---
    {
        const float* ibase = sh_a1 + lane * STR + w * 32;   // group of oc block = w
        ull inp[16];
#pragma unroll
        for (int q = 0; q < 16; q++) inp[q] = *(const ull*)(ibase + 2 * q);

        const bool valid = (t0 + lane) < L2;
        for (int ocl = 0; ocl < 32; ocl++) {
            int oc = w * 32 + ocl;
            const ulonglong2* wr = (const ulonglong2*)(sw2 + oc * 32);  // broadcast
            ull acc = 0ULL;
#pragma unroll
            for (int q = 0; q < 8; q++) {
                ulonglong2 u = wr[q];
                acc = ffma2(inp[2 * q],     u.x, acc);
                acc = ffma2(inp[2 * q + 1], u.y, acc);
            }
            float2 s = unpk(acc);
            float val = s.x + s.y + __ldg(ba2 + oc);
            float sig = 1.f / (1.f + __expf(-val));
            float h   = sh_ht[lane * STR + oc];
            if (valid)
                hm[((size_t)b * C_ + oc) * PADL + t0 + lane] = h * sig;
        }
    }
}

// ---------------------------------------------------------------------------
extern "C" void kernel_launch(void* const* d_in, const int* in_sizes, int n_in,
                              void* d_out, int out_size)
{
    const float* x   = (const float*)d_in[0];
    const float* w1  = (const float*)d_in[1];
    const float* b1  = (const float*)d_in[2];
    const float* w2  = (const float*)d_in[3];
    const float* b2  = (const float*)d_in[4];
    const float* wa1 = (const float*)d_in[5];
    const float* ba1 = (const float*)d_in[6];
    const float* wa2 = (const float*)d_in[7];
    const float* ba2 = (const float*)d_in[8];
    const float* w3  = (const float*)d_in[9];
    const float* b3  = (const float*)d_in[10];
    float* y = (float*)d_out;

    float *h1p, *h2p, *hmp;
    cudaGetSymbolAddress((void**)&h1p, g_h1);
    cudaGetSymbolAddress((void**)&h2p, g_h2);
    cudaGetSymbolAddress((void**)&hmp, g_hm);

    const int SM3 = 32 * RS * 4 + 32 * 3 * 32 * 8 + 32 * 8;   // 91392
    const int SM5 = 32 * RS * 4 + 32 * 5 * 32 * 8 + 32 * 8;   // 107776
    const int SMA = (16384 + 8192 + 3 * 32 * STR) * 4;        // 197376

    cudaFuncSetAttribute(conv_kernel<3, true>,  cudaFuncAttributeMaxDynamicSharedMemorySize, SM3);
    cudaFuncSetAttribute(conv_kernel<5, false>, cudaFuncAttributeMaxDynamicSharedMemorySize, SM5);
    cudaFuncSetAttribute(attn_kernel,           cudaFuncAttributeMaxDynamicSharedMemorySize, SMA);

    // conv1 + shuffle : x[*,4096] -> g_h1[*,4094] (padded stride 4096)
    conv_kernel<3, true><<<dim3(8, 8, B_), 256, SM3>>>(x, L0, L0, h1p, L1, PADL, w1, b1);
    // conv2 + shuffle : g_h1 -> g_h2[*,4092]
    conv_kernel<3, true><<<dim3(8, 8, B_), 256, SM3>>>(h1p, L1, PADL, h2p, L2, PADL, w2, b2);
    // sort attention  : g_h2 -> g_hm
    attn_kernel<<<dim3(128, B_), 256, SMA>>>(h2p, hmp, wa1, ba1, wa2, ba2);
    // conv3 (K=5)     : g_hm -> y[*,4088]
    conv_kernel<5, false><<<dim3(8, 8, B_), 256, SM5>>>(hmp, L2, PADL, y, L4, L4, w3, b3);
}

// round 10
// speedup vs baseline: 1.2943x; 1.0683x over previous
#include <cuda_runtime.h>
#include <cuda_bf16.h>

// ---------------------------------------------------------------------------
// FSSConv1dCell: conv3(g8)+shuffle -> conv3(g8)+shuffle -> sortattn -> conv5(g8)
// B=8, C=256, L=4096, groups=8, cpg=32
// ---------------------------------------------------------------------------

typedef unsigned long long ull;

#define B_  8
#define C_  256
#define L0  4096
#define L1  4094   // after conv1 (K=3)
#define L2  4092   // after conv2 (K=3)
#define L4  4088   // after conv3 (K=5)
#define PADL 4096  // row stride of intermediate buffers
#define STR  258   // attn smem column stride

// intermediate buffers (device globals: no allocation allowed)
__device__ float g_h1[B_ * C_ * PADL];
__device__ float g_h2[B_ * C_ * PADL];
__device__ float g_hm[B_ * C_ * PADL];

// ---- packed f32x2 helpers (sm_103a FFMA2 path, PTX-only) ----
__device__ __forceinline__ ull pk2(float lo, float hi) {
    ull r; asm("mov.b64 %0, {%1,%2};" : "=l"(r) : "f"(lo), "f"(hi)); return r;
}
__device__ __forceinline__ ull ffma2(ull a, ull b, ull c) {
    ull d; asm("fma.rn.f32x2 %0, %1, %2, %3;" : "=l"(d) : "l"(a), "l"(b), "l"(c)); return d;
}
__device__ __forceinline__ ull addf2(ull a, ull b) {
    ull d; asm("add.rn.f32x2 %0, %1, %2;" : "=l"(d) : "l"(a), "l"(b)); return d;
}
__device__ __forceinline__ float2 unpk(ull v) {
    float2 f; asm("mov.b64 {%0,%1}, %2;" : "=f"(f.x), "=f"(f.y) : "l"(v)); return f;
}

// ---------------------------------------------------------------------------
// grouped conv1d, K taps, optional channel shuffle on output.
// block: 256 threads, __launch_bounds__(256,3) -> 3 blocks/SM.
// tile: 256 output columns, one (batch, group) per block.
// thread: cg = tid&31 -> 8 columns, cq = tid>>5 -> 4 out channels.
// smem: in tile [32][264], dup weights float2 [32][K][32], dup bias [32]
// ---------------------------------------------------------------------------
#define RS 264

template <int K, bool SHUF>
__global__ __launch_bounds__(256, 3)
void conv_kernel(const float* __restrict__ in, int Lin, int inStride,
                 float* __restrict__ out, int Lout, int outStride,
                 const float* __restrict__ w, const float* __restrict__ bias)
{
    extern __shared__ float smem[];
    float*  sh_in = smem;                                 // 32*RS
    float2* sh_wd = (float2*)(smem + 32 * RS);            // [32][K][32]
    float2* sh_bd = sh_wd + 32 * K * 32;                  // [32]

    const int tid  = threadIdx.x;
    const int tile = blockIdx.x, gidx = blockIdx.y, b = blockIdx.z;
    const int t0 = tile * 256;
    const int g0 = gidx * 32;

    // --- stage input tile (group's 32 channels, cols t0 .. t0+255+K-1) ---
    {
        int ci = tid >> 3, l8 = tid & 7;
        const float* rp = in + ((size_t)b * C_ + g0 + ci) * (size_t)inStride;
        for (int j = l8 * 4; j < 256 + K - 1; j += 32) {
            int c0 = t0 + j;
            float4 v;
            if (c0 + 3 < Lin) {
                v = *(const float4*)(rp + c0);
            } else {
                v.x = (c0     < Lin) ? rp[c0]     : 0.f;
                v.y = (c0 + 1 < Lin) ? rp[c0 + 1] : 0.f;
                v.z = (c0 + 2 < Lin) ? rp[c0 + 2] : 0.f;
                v.w = (c0 + 3 < Lin) ? rp[c0 + 3] : 0.f;
            }
            *(float4*)&sh_in[ci * RS + j] = v;
        }
    }
    // --- stage duplicated weights [ci][k][co] and bias ---
    for (int idx = tid; idx < 32 * K * 32; idx += 256) {
        int ci = idx / (K * 32), r = idx % (K * 32);
        int k = r >> 5, co = r & 31;
        float v = w[((size_t)(g0 + co)) * (32 * K) + ci * K + k];
        sh_wd[idx] = make_float2(v, v);
    }
    if (tid < 32) { float v = bias[g0 + tid]; sh_bd[tid] = make_float2(v, v); }
    __syncthreads();

    const int cg = tid & 31;   // column group: 8 columns
    const int cq = tid >> 5;   // out-channel group: 4 channels

    ull acc[4][4];
#pragma unroll
    for (int r = 0; r < 4; r++) {
        ull bb = *(const ull*)&sh_bd[cq * 4 + r];
        acc[r][0] = bb; acc[r][1] = bb; acc[r][2] = bb; acc[r][3] = bb;
    }

    const float* ip = &sh_in[cg * 8];
#pragma unroll 4
    for (int ci = 0; ci < 32; ci++) {
        const float* row = ip + ci * RS;
        float v[K + 7];
        float4 t4 = *(const float4*)(row);
        float4 u4 = *(const float4*)(row + 4);
        v[0] = t4.x; v[1] = t4.y; v[2] = t4.z; v[3] = t4.w;
        v[4] = u4.x; v[5] = u4.y; v[6] = u4.z; v[7] = u4.w;
        if (K == 3) {
            float2 t2 = *(const float2*)(row + 8);
            v[8] = t2.x; v[9] = t2.y;
        } else {
            float4 w4 = *(const float4*)(row + 8);
            v[8] = w4.x; v[9] = w4.y; v[10] = w4.z; v[11] = w4.w;
        }
        // pairs pr[j] = (v[j], v[j+1]); acc[.][m] needs pr[k+2m], k<K, m<4
        ull pr[K + 6];
#pragma unroll
        for (int j = 0; j < K + 6; j++) pr[j] = pk2(v[j], v[j + 1]);

        const float2* wrow = &sh_wd[ci * K * 32];
#pragma unroll
        for (int r = 0; r < 4; r++) {
#pragma unroll
            for (int k = 0; k < K; k++) {
                ull wk = *(const ull*)&wrow[k * 32 + cq * 4 + r];
                acc[r][0] = ffma2(pr[k],     wk, acc[r][0]);
                acc[r][1] = ffma2(pr[k + 2], wk, acc[r][1]);
                acc[r][2] = ffma2(pr[k + 4], wk, acc[r][2]);
                acc[r][3] = ffma2(pr[k + 6], wk, acc[r][3]);
            }
        }
    }

    // --- store (optionally shuffled: c' = co*8 + gidx) ---
    const int colBase = t0 + cg * 8;
#pragma unroll
    for (int r = 0; r < 4; r++) {
        int co = cq * 4 + r;
        int oc = SHUF ? (co * 8 + gidx) : (g0 + co);
        float* op = out + ((size_t)b * C_ + oc) * (size_t)outStride;
        float2 a0 = unpk(acc[r][0]), a1 = unpk(acc[r][1]);
        float2 a2 = unpk(acc[r][2]), a3 = unpk(acc[r][3]);
        if (colBase + 7 < Lout) {
            float4 q0; q0.x = a0.x; q0.y = a0.y; q0.z = a1.x; q0.w = a1.y;
            float4 q1; q1.x = a2.x; q1.y = a2.y; q1.z = a3.x; q1.w = a3.y;
            *(float4*)(op + colBase)     = q0;
            *(float4*)(op + colBase + 4) = q1;
        } else {
            float vv[8] = {a0.x, a0.y, a1.x, a1.y, a2.x, a2.y, a3.x, a3.y};
#pragma unroll
            for (int m = 0; m < 8; m++)
                if (colBase + m < Lout) op[colBase + m] = vv[m];
        }
    }
}

// ---------------------------------------------------------------------------
// warp-level bitonic sort of 256 values, 8 regs/lane, element e = r*32 + lane
// ---------------------------------------------------------------------------
__device__ __forceinline__ void bitonic256(float v[8], int lane) {
#pragma unroll
    for (int k = 2; k <= 256; k <<= 1) {
#pragma unroll
        for (int j = k >> 1; j > 0; j >>= 1) {
            if (j >= 32) {
                int jr = j >> 5;
#pragma unroll
                for (int r = 0; r < 8; r++) {
                    if ((r & jr) == 0) {
                        int r2 = r | jr;
                        bool up = (((r * 32) & k) == 0);
                        float a = v[r], b = v[r2];
                        float mn = fminf(a, b), mx = fmaxf(a, b);
                        v[r]  = up ? mn : mx;
                        v[r2] = up ? mx : mn;
                    }
                }
            } else {
#pragma unroll
                for (int r = 0; r < 8; r++) {
                    int e = r * 32 + lane;
                    float p = __shfl_xor_sync(0xffffffffu, v[r], j);
                    bool keepMin = (((e & j) == 0) == ((e & k) == 0));
                    v[r] = keepMin ? fminf(v[r], p) : fmaxf(v[r], p);
                }
            }
        }
    }
}

// ---------------------------------------------------------------------------
// SortAttn fused kernel:  h2 -> hm = h2 * sigmoid(conv_a2(shuffle(conv_a1(cat(sort(h2),h2)))))
// block: 256 threads (8 warps), __launch_bounds__(256,2) -> 2 blocks/SM.
// tile = 32 columns of one batch.
//   stage:   warp w loads channels w*32..w*32+31 coalesced -> sh_ht[col][ch].
//   sort:    warp w sorts cols w*4..w*4+3 -> sh_srt[col][rank].
//   conv_a1: warp w = oc-group w (g=8 concat split: groups 0-3 read sorted,
//            4-7 read h). lane = column; inputs in 32 f32x2 regs; weights via
//            uniform __ldg LDG.128 (L1-cached, broadcast); 4-way acc split.
//   conv_a2: same on shuffled a1, sigmoid gate, coalesced STG.
// ---------------------------------------------------------------------------
__global__ __launch_bounds__(256, 2)
void attn_kernel(const float* __restrict__ h2, float* __restrict__ hm,
                 const float* __restrict__ wa1, const float* __restrict__ ba1,
                 const float* __restrict__ wa2, const float* __restrict__ ba2)
{
    extern __shared__ float smem[];
    float* sh_ht  = smem;                       // [32][STR]  h transposed
    float* sh_srt = sh_ht  + 32 * STR;          // [32][STR]  sorted
    float* sh_a1  = sh_srt + 32 * STR;          // [32][STR]  a1 shuffled transposed

    const int tid = threadIdx.x, lane = tid & 31, w = tid >> 5;
    const int b = blockIdx.y;
    const int t0 = blockIdx.x * 32;

    // --- stage h2 tile transposed: warp w handles channels w*32..w*32+31 ---
    {
        int ch4 = lane >> 3, colq = lane & 7;   // 4 channels x 8 float4-cols per iter
        int c0 = t0 + colq * 4;
#pragma unroll
        for (int it = 0; it < 8; it++) {
            int ch = w * 32 + it * 4 + ch4;
            const float* rp = h2 + ((size_t)b * C_ + ch) * PADL + c0;
            float4 v;
            if (c0 + 3 < L2) {
                v = *(const float4*)rp;
            } else {
                v.x = (c0     < L2) ? rp[0] : 0.f;
                v.y = (c0 + 1 < L2) ? rp[1] : 0.f;
                v.z = (c0 + 2 < L2) ? rp[2] : 0.f;
                v.w = (c0 + 3 < L2) ? rp[3] : 0.f;
            }
            sh_ht[(colq * 4 + 0) * STR + ch] = v.x;
            sh_ht[(colq * 4 + 1) * STR + ch] = v.y;
            sh_ht[(colq * 4 + 2) * STR + ch] = v.z;
            sh_ht[(colq * 4 + 3) * STR + ch] = v.w;
        }
    }
    __syncthreads();

    // --- sort: warp w sorts columns w*4 .. w*4+3 ---
#pragma unroll
    for (int cc = 0; cc < 4; cc++) {
        int col = w * 4 + cc;
        float v[8];
#pragma unroll
        for (int r = 0; r < 8; r++) v[r] = sh_ht[col * STR + r * 32 + lane];
        bitonic256(v, lane);
#pragma unroll
        for (int r = 0; r < 8; r++) sh_srt[col * STR + r * 32 + lane] = v[r];
    }
    __syncthreads();

    // --- conv_a1: warp w = group w; lane = column ---
    {
        const float* ibase = (w < 4 ? sh_srt : sh_ht) + lane * STR + (w & 3) * 64;
        ull inp[32];
#pragma unroll
        for (int q = 0; q < 32; q++) inp[q] = *(const ull*)(ibase + 2 * q);

#pragma unroll 2
        for (int ocl = 0; ocl < 32; ocl++) {
            int oc = w * 32 + ocl;
            const ulonglong2* wr = (const ulonglong2*)(wa1 + oc * 64);  // uniform LDG
            ull s0 = 0, s1 = 0, s2 = 0, s3 = 0;
#pragma unroll
            for (int q = 0; q < 8; q++) {
                ulonglong2 u0 = __ldg(wr + 2 * q);
                ulonglong2 u1 = __ldg(wr + 2 * q + 1);
                s0 = ffma2(inp[4 * q],     u0.x, s0);
                s1 = ffma2(inp[4 * q + 1], u0.y, s1);
                s2 = ffma2(inp[4 * q + 2], u1.x, s2);
                s3 = ffma2(inp[4 * q + 3], u1.y, s3);
            }
            float2 s = unpk(addf2(addf2(s0, s1), addf2(s2, s3)));
            float val = s.x + s.y + __ldg(ba1 + oc);
            // shuffled channel: c' = (oc&31)*8 + (oc>>5) = ocl*8 + w
            sh_a1[lane * STR + ocl * 8 + w] = val;
        }
    }
    __syncthreads();

    // --- conv_a2 + sigmoid gate + store ---
    {
        const float* ibase = sh_a1 + lane * STR + w * 32;   // group of oc block = w
        ull inp[16];
#pragma unroll
        for (int q = 0; q < 16; q++) inp[q] = *(const ull*)(ibase + 2 * q);

        const bool valid = (t0 + lane) < L2;
#pragma unroll 2
        for (int ocl = 0; ocl < 32; ocl++) {
            int oc = w * 32 + ocl;
            const ulonglong2* wr = (const ulonglong2*)(wa2 + oc * 32);  // uniform LDG
            ull s0 = 0, s1 = 0, s2 = 0, s3 = 0;
#pragma unroll
            for (int q = 0; q < 4; q++) {
                ulonglong2 u0 = __ldg(wr + 2 * q);
                ulonglong2 u1 = __ldg(wr + 2 * q + 1);
                s0 = ffma2(inp[4 * q],     u0.x, s0);
                s1 = ffma2(inp[4 * q + 1], u0.y, s1);
                s2 = ffma2(inp[4 * q + 2], u1.x, s2);
                s3 = ffma2(inp[4 * q + 3], u1.y, s3);
            }
            float2 s = unpk(addf2(addf2(s0, s1), addf2(s2, s3)));
            float val = s.x + s.y + __ldg(ba2 + oc);
            float sig = 1.f / (1.f + __expf(-val));
            float h   = sh_ht[lane * STR + oc];
            if (valid)
                hm[((size_t)b * C_ + oc) * PADL + t0 + lane] = h * sig;
        }
    }
}

// ---------------------------------------------------------------------------
extern "C" void kernel_launch(void* const* d_in, const int* in_sizes, int n_in,
                              void* d_out, int out_size)
{
    const float* x   = (const float*)d_in[0];
    const float* w1  = (const float*)d_in[1];
    const float* b1  = (const float*)d_in[2];
    const float* w2  = (const float*)d_in[3];
    const float* b2  = (const float*)d_in[4];
    const float* wa1 = (const float*)d_in[5];
    const float* ba1 = (const float*)d_in[6];
    const float* wa2 = (const float*)d_in[7];
    const float* ba2 = (const float*)d_in[8];
    const float* w3  = (const float*)d_in[9];
    const float* b3  = (const float*)d_in[10];
    float* y = (float*)d_out;

    float *h1p, *h2p, *hmp;
    cudaGetSymbolAddress((void**)&h1p, g_h1);
    cudaGetSymbolAddress((void**)&h2p, g_h2);
    cudaGetSymbolAddress((void**)&hmp, g_hm);

    const int SM3 = 32 * RS * 4 + 32 * 3 * 32 * 8 + 32 * 8;   // 58624
    const int SM5 = 32 * RS * 4 + 32 * 5 * 32 * 8 + 32 * 8;   // 75008
    const int SMA = 3 * 32 * STR * 4;                         // 99072

    cudaFuncSetAttribute(conv_kernel<3, true>,  cudaFuncAttributeMaxDynamicSharedMemorySize, SM3);
    cudaFuncSetAttribute(conv_kernel<5, false>, cudaFuncAttributeMaxDynamicSharedMemorySize, SM5);
    cudaFuncSetAttribute(attn_kernel,           cudaFuncAttributeMaxDynamicSharedMemorySize, SMA);

    // conv1 + shuffle : x[*,4096] -> g_h1[*,4094] (padded stride 4096)
    conv_kernel<3, true><<<dim3(16, 8, B_), 256, SM3>>>(x, L0, L0, h1p, L1, PADL, w1, b1);
    // conv2 + shuffle : g_h1 -> g_h2[*,4092]
    conv_kernel<3, true><<<dim3(16, 8, B_), 256, SM3>>>(h1p, L1, PADL, h2p, L2, PADL, w2, b2);
    // sort attention  : g_h2 -> g_hm
    attn_kernel<<<dim3(128, B_), 256, SMA>>>(h2p, hmp, wa1, ba1, wa2, ba2);
    // conv3 (K=5)     : g_hm -> y[*,4088]
    conv_kernel<5, false><<<dim3(16, 8, B_), 256, SM5>>>(hmp, L2, PADL, y, L4, L4, w3, b3);
}

// round 11
// speedup vs baseline: 1.4414x; 1.1136x over previous
#include <cuda_runtime.h>
#include <cuda_bf16.h>

// ---------------------------------------------------------------------------
// FSSConv1dCell: conv3(g8)+shuffle -> conv3(g8)+shuffle -> sortattn -> conv5(g8)
// B=8, C=256, L=4096, groups=8, cpg=32
// ---------------------------------------------------------------------------

typedef unsigned long long ull;

#define B_  8
#define C_  256
#define L0  4096
#define L1  4094   // after conv1 (K=3)
#define L2  4092   // after conv2 (K=3)
#define L4  4088   // after conv3 (K=5)
#define PADL 4096  // row stride of intermediate buffers
#define STR  258   // attn smem column stride

// intermediate buffers (device globals: no allocation allowed)
__device__ float g_h1[B_ * C_ * PADL];
__device__ float g_h2[B_ * C_ * PADL];
__device__ float g_hm[B_ * C_ * PADL];

// ---- packed f32x2 helpers (sm_103a FFMA2 path, PTX-only) ----
__device__ __forceinline__ ull pk2(float lo, float hi) {
    ull r; asm("mov.b64 %0, {%1,%2};" : "=l"(r) : "f"(lo), "f"(hi)); return r;
}
__device__ __forceinline__ ull ffma2(ull a, ull b, ull c) {
    ull d; asm("fma.rn.f32x2 %0, %1, %2, %3;" : "=l"(d) : "l"(a), "l"(b), "l"(c)); return d;
}
__device__ __forceinline__ ull addf2(ull a, ull b) {
    ull d; asm("add.rn.f32x2 %0, %1, %2;" : "=l"(d) : "l"(a), "l"(b)); return d;
}
__device__ __forceinline__ float2 unpk(ull v) {
    float2 f; asm("mov.b64 {%0,%1}, %2;" : "=f"(f.x), "=f"(f.y) : "l"(v)); return f;
}

// ---------------------------------------------------------------------------
// prep: tiny deterministic launch. Exists so the captured graph has 5 nodes
// and ncu's fixed "-s 5 -c 1" window lands on attn_kernel (profiling aid).
// Writes zeros into never-read pad columns of g_h1.
// ---------------------------------------------------------------------------
__global__ void prep_kernel() {
    if (threadIdx.x < 2) g_h1[L1 + threadIdx.x] = 0.f;
}

// ---------------------------------------------------------------------------
// grouped conv1d, K taps, optional channel shuffle on output.
// block: 256 threads, __launch_bounds__(256,3) -> 3 blocks/SM.
// tile: 256 output columns, one (batch, group) per block.
// thread: cg = tid&31 -> 8 columns, cq = tid>>5 -> 4 out channels.
// smem: in tile [32][264], dup weights float2 [32][K][32], dup bias [32]
// ---------------------------------------------------------------------------
#define RS 264

template <int K, bool SHUF>
__global__ __launch_bounds__(256, 3)
void conv_kernel(const float* __restrict__ in, int Lin, int inStride,
                 float* __restrict__ out, int Lout, int outStride,
                 const float* __restrict__ w, const float* __restrict__ bias)
{
    extern __shared__ float smem[];
    float*  sh_in = smem;                                 // 32*RS
    float2* sh_wd = (float2*)(smem + 32 * RS);            // [32][K][32]
    float2* sh_bd = sh_wd + 32 * K * 32;                  // [32]

    const int tid  = threadIdx.x;
    const int tile = blockIdx.x, gidx = blockIdx.y, b = blockIdx.z;
    const int t0 = tile * 256;
    const int g0 = gidx * 32;

    // --- stage input tile (group's 32 channels, cols t0 .. t0+255+K-1) ---
    {
        int ci = tid >> 3, l8 = tid & 7;
        const float* rp = in + ((size_t)b * C_ + g0 + ci) * (size_t)inStride;
        for (int j = l8 * 4; j < 256 + K - 1; j += 32) {
            int c0 = t0 + j;
            float4 v;
            if (c0 + 3 < Lin) {
                v = *(const float4*)(rp + c0);
            } else {
                v.x = (c0     < Lin) ? rp[c0]     : 0.f;
                v.y = (c0 + 1 < Lin) ? rp[c0 + 1] : 0.f;
                v.z = (c0 + 2 < Lin) ? rp[c0 + 2] : 0.f;
                v.w = (c0 + 3 < Lin) ? rp[c0 + 3] : 0.f;
            }
            *(float4*)&sh_in[ci * RS + j] = v;
        }
    }
    // --- stage duplicated weights [ci][k][co] and bias ---
    for (int idx = tid; idx < 32 * K * 32; idx += 256) {
        int ci = idx / (K * 32), r = idx % (K * 32);
        int k = r >> 5, co = r & 31;
        float v = w[((size_t)(g0 + co)) * (32 * K) + ci * K + k];
        sh_wd[idx] = make_float2(v, v);
    }
    if (tid < 32) { float v = bias[g0 + tid]; sh_bd[tid] = make_float2(v, v); }
    __syncthreads();

    const int cg = tid & 31;   // column group: 8 columns
    const int cq = tid >> 5;   // out-channel group: 4 channels

    ull acc[4][4];
#pragma unroll
    for (int r = 0; r < 4; r++) {
        ull bb = *(const ull*)&sh_bd[cq * 4 + r];
        acc[r][0] = bb; acc[r][1] = bb; acc[r][2] = bb; acc[r][3] = bb;
    }

    const float* ip = &sh_in[cg * 8];
#pragma unroll 4
    for (int ci = 0; ci < 32; ci++) {
        const float* row = ip + ci * RS;
        float v[K + 7];
        float4 t4 = *(const float4*)(row);
        float4 u4 = *(const float4*)(row + 4);
        v[0] = t4.x; v[1] = t4.y; v[2] = t4.z; v[3] = t4.w;
        v[4] = u4.x; v[5] = u4.y; v[6] = u4.z; v[7] = u4.w;
        if (K == 3) {
            float2 t2 = *(const float2*)(row + 8);
            v[8] = t2.x; v[9] = t2.y;
        } else {
            float4 w4 = *(const float4*)(row + 8);
            v[8] = w4.x; v[9] = w4.y; v[10] = w4.z; v[11] = w4.w;
        }
        // pairs pr[j] = (v[j], v[j+1]); acc[.][m] needs pr[k+2m], k<K, m<4
        ull pr[K + 6];
#pragma unroll
        for (int j = 0; j < K + 6; j++) pr[j] = pk2(v[j], v[j + 1]);

        const float2* wrow = &sh_wd[ci * K * 32];
#pragma unroll
        for (int r = 0; r < 4; r++) {
#pragma unroll
            for (int k = 0; k < K; k++) {
                ull wk = *(const ull*)&wrow[k * 32 + cq * 4 + r];
                acc[r][0] = ffma2(pr[k],     wk, acc[r][0]);
                acc[r][1] = ffma2(pr[k + 2], wk, acc[r][1]);
                acc[r][2] = ffma2(pr[k + 4], wk, acc[r][2]);
                acc[r][3] = ffma2(pr[k + 6], wk, acc[r][3]);
            }
        }
    }

    // --- store (optionally shuffled: c' = co*8 + gidx) ---
    const int colBase = t0 + cg * 8;
#pragma unroll
    for (int r = 0; r < 4; r++) {
        int co = cq * 4 + r;
        int oc = SHUF ? (co * 8 + gidx) : (g0 + co);
        float* op = out + ((size_t)b * C_ + oc) * (size_t)outStride;
        float2 a0 = unpk(acc[r][0]), a1 = unpk(acc[r][1]);
        float2 a2 = unpk(acc[r][2]), a3 = unpk(acc[r][3]);
        if (colBase + 7 < Lout) {
            float4 q0; q0.x = a0.x; q0.y = a0.y; q0.z = a1.x; q0.w = a1.y;
            float4 q1; q1.x = a2.x; q1.y = a2.y; q1.z = a3.x; q1.w = a3.y;
            *(float4*)(op + colBase)     = q0;
            *(float4*)(op + colBase + 4) = q1;
        } else {
            float vv[8] = {a0.x, a0.y, a1.x, a1.y, a2.x, a2.y, a3.x, a3.y};
#pragma unroll
            for (int m = 0; m < 8; m++)
                if (colBase + m < Lout) op[colBase + m] = vv[m];
        }
    }
}

// ---------------------------------------------------------------------------
// warp-level bitonic sort of 256 values, 8 regs/lane, element e = r*32 + lane
// ---------------------------------------------------------------------------
__device__ __forceinline__ void bitonic256(float v[8], int lane) {
#pragma unroll
    for (int k = 2; k <= 256; k <<= 1) {
#pragma unroll
        for (int j = k >> 1; j > 0; j >>= 1) {
            if (j >= 32) {
                int jr = j >> 5;
#pragma unroll
                for (int r = 0; r < 8; r++) {
                    if ((r & jr) == 0) {
                        int r2 = r | jr;
                        bool up = (((r * 32) & k) == 0);
                        float a = v[r], b = v[r2];
                        float mn = fminf(a, b), mx = fmaxf(a, b);
                        v[r]  = up ? mn : mx;
                        v[r2] = up ? mx : mn;
                    }
                }
            } else {
#pragma unroll
                for (int r = 0; r < 8; r++) {
                    int e = r * 32 + lane;
                    float p = __shfl_xor_sync(0xffffffffu, v[r], j);
                    bool keepMin = (((e & j) == 0) == ((e & k) == 0));
                    v[r] = keepMin ? fminf(v[r], p) : fmaxf(v[r], p);
                }
            }
        }
    }
}

// ---------------------------------------------------------------------------
// SortAttn fused kernel:  h2 -> hm = h2 * sigmoid(conv_a2(shuffle(conv_a1(cat(sort(h2),h2)))))
// block: 512 threads (16 warps), 1 block/SM (smem 195KB). tile = 32 columns.
//   stage:   warp w loads channels w*16..w*16+15 coalesced -> sh_ht[col][ch].
//   sort:    warp w sorts cols w*2, w*2+1 -> sh_srt[col][rank].
//   conv_a1: warp pair (g = w>>1) = oc-group g (g=8 concat split: groups 0-3
//            read sorted, 4-7 read h); warp handles 16 of the 32 ocs.
//            lane = column; inputs in 32 f32x2 regs; weights broadcast LDS.128
//            from smem (no dup; consecutive-j pairing); 4-way acc split.
//   conv_a2: same on shuffled a1, sigmoid gate, coalesced STG.
// ---------------------------------------------------------------------------
__global__ __launch_bounds__(512, 1)
void attn_kernel(const float* __restrict__ h2, float* __restrict__ hm,
                 const float* __restrict__ wa1, const float* __restrict__ ba1,
                 const float* __restrict__ wa2, const float* __restrict__ ba2)
{
    extern __shared__ float smem[];
    float* sw1    = smem;                       // 16384 floats (wa1 [256][64])
    float* sw2    = smem + 16384;               // 8192  floats (wa2 [256][32])
    float* sh_ht  = smem + 24576;               // [32][STR]  h transposed
    float* sh_srt = sh_ht  + 32 * STR;          // [32][STR]  sorted
    float* sh_a1  = sh_srt + 32 * STR;          // [32][STR]  a1 shuffled transposed

    const int tid = threadIdx.x, lane = tid & 31, w = tid >> 5;
    const int b = blockIdx.y;
    const int t0 = blockIdx.x * 32;

    // --- stage weights into smem (raw layout; consecutive j = natural pairs)
    {
        const float4* sp1 = (const float4*)wa1; float4* dp1 = (float4*)sw1;
        for (int i = tid; i < 4096; i += 512) dp1[i] = sp1[i];
        const float4* sp2 = (const float4*)wa2; float4* dp2 = (float4*)sw2;
        for (int i = tid; i < 2048; i += 512) dp2[i] = sp2[i];
    }

    // --- stage h2 tile transposed: warp w handles channels w*16..w*16+15 ---
    {
        int chq = lane >> 3, colq = lane & 7;   // 4 channels x 8 float4-cols
        int c0 = t0 + colq * 4;
#pragma unroll
        for (int it = 0; it < 4; it++) {
            int ch = w * 16 + it * 4 + chq;
            const float* rp = h2 + ((size_t)b * C_ + ch) * PADL + c0;
            float4 v;
            if (c0 + 3 < L2) {
                v = *(const float4*)rp;
            } else {
                v.x = (c0     < L2) ? rp[0] : 0.f;
                v.y = (c0 + 1 < L2) ? rp[1] : 0.f;
                v.z = (c0 + 2 < L2) ? rp[2] : 0.f;
                v.w = (c0 + 3 < L2) ? rp[3] : 0.f;
            }
            sh_ht[(colq * 4 + 0) * STR + ch] = v.x;
            sh_ht[(colq * 4 + 1) * STR + ch] = v.y;
            sh_ht[(colq * 4 + 2) * STR + ch] = v.z;
            sh_ht[(colq * 4 + 3) * STR + ch] = v.w;
        }
    }
    __syncthreads();

    // --- sort: warp w sorts columns w*2, w*2+1 ---
#pragma unroll
    for (int cc = 0; cc < 2; cc++) {
        int col = w * 2 + cc;
        float v[8];
#pragma unroll
        for (int r = 0; r < 8; r++) v[r] = sh_ht[col * STR + r * 32 + lane];
        bitonic256(v, lane);
#pragma unroll
        for (int r = 0; r < 8; r++) sh_srt[col * STR + r * 32 + lane] = v[r];
    }
    __syncthreads();

    const int g = w >> 1;        // oc-group (0..7), two warps per group
    const int half = w & 1;      // which 16 ocs of the group

    // --- conv_a1: lane = column; 16 ocs per warp ---
    {
        const float* ibase = (g < 4 ? sh_srt : sh_ht) + lane * STR + (g & 3) * 64;
        ull inp[32];
#pragma unroll
        for (int q = 0; q < 32; q++) inp[q] = *(const ull*)(ibase + 2 * q);

        for (int i = 0; i < 16; i++) {
            int ocl = half * 16 + i;
            int oc = g * 32 + ocl;
            const ulonglong2* wr = (const ulonglong2*)(sw1 + oc * 64);  // broadcast
            ull a0 = 0, a1 = 0, a2 = 0, a3 = 0;
#pragma unroll
            for (int q = 0; q < 8; q++) {
                ulonglong2 u0 = wr[2 * q];
                ulonglong2 u1 = wr[2 * q + 1];
                a0 = ffma2(inp[4 * q],     u0.x, a0);
                a1 = ffma2(inp[4 * q + 1], u0.y, a1);
                a2 = ffma2(inp[4 * q + 2], u1.x, a2);
                a3 = ffma2(inp[4 * q + 3], u1.y, a3);
            }
            float2 s = unpk(addf2(addf2(a0, a1), addf2(a2, a3)));
            float val = s.x + s.y + __ldg(ba1 + oc);
            // shuffled channel: c' = (oc&31)*8 + (oc>>5) = ocl*8 + g
            sh_a1[lane * STR + ocl * 8 + g] = val;
        }
    }
    __syncthreads();

    // --- conv_a2 + sigmoid gate + store ---
    {
        const float* ibase = sh_a1 + lane * STR + g * 32;   // group of oc block
        ull inp[16];
#pragma unroll
        for (int q = 0; q < 16; q++) inp[q] = *(const ull*)(ibase + 2 * q);

        const bool valid = (t0 + lane) < L2;
        for (int i = 0; i < 16; i++) {
            int oc = g * 32 + half * 16 + i;
            const ulonglong2* wr = (const ulonglong2*)(sw2 + oc * 32);  // broadcast
            ull a0 = 0, a1 = 0, a2 = 0, a3 = 0;
#pragma unroll
            for (int q = 0; q < 4; q++) {
                ulonglong2 u0 = wr[2 * q];
                ulonglong2 u1 = wr[2 * q + 1];
                a0 = ffma2(inp[4 * q],     u0.x, a0);
                a1 = ffma2(inp[4 * q + 1], u0.y, a1);
                a2 = ffma2(inp[4 * q + 2], u1.x, a2);
                a3 = ffma2(inp[4 * q + 3], u1.y, a3);
            }
            float2 s = unpk(addf2(addf2(a0, a1), addf2(a2, a3)));
            float val = s.x + s.y + __ldg(ba2 + oc);
            float sig = 1.f / (1.f + __expf(-val));
            float h   = sh_ht[lane * STR + oc];
            if (valid)
                hm[((size_t)b * C_ + oc) * PADL + t0 + lane] = h * sig;
        }
    }
}

// ---------------------------------------------------------------------------
extern "C" void kernel_launch(void* const* d_in, const int* in_sizes, int n_in,
                              void* d_out, int out_size)
{
    const float* x   = (const float*)d_in[0];
    const float* w1  = (const float*)d_in[1];
    const float* b1  = (const float*)d_in[2];
    const float* w2  = (const float*)d_in[3];
    const float* b2  = (const float*)d_in[4];
    const float* wa1 = (const float*)d_in[5];
    const float* ba1 = (const float*)d_in[6];
    const float* wa2 = (const float*)d_in[7];
    const float* ba2 = (const float*)d_in[8];
    const float* w3  = (const float*)d_in[9];
    const float* b3  = (const float*)d_in[10];
    float* y = (float*)d_out;

    float *h1p, *h2p, *hmp;
    cudaGetSymbolAddress((void**)&h1p, g_h1);
    cudaGetSymbolAddress((void**)&h2p, g_h2);
    cudaGetSymbolAddress((void**)&hmp, g_hm);

    const int SM3 = 32 * RS * 4 + 32 * 3 * 32 * 8 + 32 * 8;   // 58624
    const int SM5 = 32 * RS * 4 + 32 * 5 * 32 * 8 + 32 * 8;   // 75008
    const int SMA = (16384 + 8192 + 3 * 32 * STR) * 4;        // 197376

    cudaFuncSetAttribute(conv_kernel<3, true>,  cudaFuncAttributeMaxDynamicSharedMemorySize, SM3);
    cudaFuncSetAttribute(conv_kernel<5, false>, cudaFuncAttributeMaxDynamicSharedMemorySize, SM5);
    cudaFuncSetAttribute(attn_kernel,           cudaFuncAttributeMaxDynamicSharedMemorySize, SMA);

    prep_kernel<<<1, 32>>>();

    // conv1 + shuffle : x[*,4096] -> g_h1[*,4094] (padded stride 4096)
    conv_kernel<3, true><<<dim3(16, 8, B_), 256, SM3>>>(x, L0, L0, h1p, L1, PADL, w1, b1);
    // conv2 + shuffle : g_h1 -> g_h2[*,4092]
    conv_kernel<3, true><<<dim3(16, 8, B_), 256, SM3>>>(h1p, L1, PADL, h2p, L2, PADL, w2, b2);
    // sort attention  : g_h2 -> g_hm
    attn_kernel<<<dim3(128, B_), 512, SMA>>>(h2p, hmp, wa1, ba1, wa2, ba2);
    // conv3 (K=5)     : g_hm -> y[*,4088]
    conv_kernel<5, false><<<dim3(16, 8, B_), 256, SM5>>>(hmp, L2, PADL, y, L4, L4, w3, b3);
}